// round 7
// baseline (speedup 1.0000x reference)
#include <cuda_runtime.h>
#include <cuda_bf16.h>
#include <cstdint>

#define B 8
#define N 65536
#define C 256
#define NS 1024
#define K1 259              // real K of layer 1 (3 xyz + 256 feat)
#define KP 272              // padded K (multiple of 16)
#define M 128
#define MH 64               // M per block
#define NT 64
#define KT 16
#define EPS 1e-5f
#define NB 256              // persistent grid size
#define PPT 256             // points per thread in ballquery (256 thr)

// ---------------- scratch (device globals; no allocs) ---------------------
__device__ __align__(256) int      d_inds[B][NS];
__device__ __align__(256) float    d_gxyz[B][3][NS];
__device__ __align__(256) float    d_y1[B][M][NS];
__device__ __align__(256) float    d_y2[B][M][NS];
__device__ __align__(256) float    d_wT1[KP][M];
__device__ __align__(256) float    d_wT2[M][M];
__device__ __align__(256) float    d_wT3[M][M];
__device__ __align__(256) float    d_sum [3][M];
__device__ __align__(256) float    d_sum2[3][M];
__device__ __align__(256) unsigned d_maxenc[B][M];
__device__ __align__(256) unsigned d_minenc[B][M];
__device__ unsigned g_ctr;      // zero-init; self-resetting
__device__ unsigned g_sense;    // zero-init; parity rolls forward

__device__ __forceinline__ unsigned enc(float f) {
    unsigned u = __float_as_uint(f);
    return (u & 0x80000000u) ? ~u : (u | 0x80000000u);
}
__device__ __forceinline__ float dec(unsigned u) {
    return __uint_as_float((u & 0x80000000u) ? (u ^ 0x80000000u) : ~u);
}

// ---- grid-wide barrier (sense reversal; ctr resets each use) --------------
__device__ __forceinline__ void gbar(unsigned* s_sense) {
    __syncthreads();
    if (threadIdx.x == 0) {
        unsigned my = *s_sense;
        __threadfence();
        unsigned old = atomicAdd(&g_ctr, 1);
        if (old == NB - 1) {
            atomicExch(&g_ctr, 0);
            __threadfence();
            atomicExch(&g_sense, my ^ 1u);
        } else {
            while (atomicAdd(&g_sense, 0u) != (my ^ 1u)) __nanosleep(64);
        }
        __threadfence();
        *s_sense = my ^ 1u;
    }
    __syncthreads();
}

// ---- gemm phase body (inlined per layer) ----------------------------------
template<int K, int LAYER>
__device__ __forceinline__ void gemm_phase(
    const float* __restrict__ feat,
    const float* __restrict__ bias,
    const float* __restrict__ gamma_prev,
    const float* __restrict__ beta_prev,
    float (*As)[MH], float (*Bs)[NT],
    float (*red)[MH + 1], float (*red2)[MH + 1],
    float* s_scale, float* s_shift, int* s_inds)
{
    int blk = blockIdx.x;
    int b   = blk >> 5;
    int m0  = ((blk >> 4) & 1) * MH;
    int n0  = (blk & 15) * NT;
    int tid = threadIdx.x;               // 256
    int tm  = (tid & 15) * 4;
    int tn  = (tid >> 4) * 4;
    int g   = tid >> 4;

    if (LAYER == 0) {
        if (tid < NT) s_inds[tid] = d_inds[b][n0 + tid];
    } else {
        if (tid < M) {
            float inv = 1.0f / (float)(B * NS);
            float mn  = d_sum [LAYER-1][tid] * inv;
            float var = d_sum2[LAYER-1][tid] * inv - mn * mn;
            float a = gamma_prev[tid] * rsqrtf(var + EPS);
            s_scale[tid] = a;
            s_shift[tid] = beta_prev[tid] - mn * a;
        }
    }
    __syncthreads();

    float acc[4][4] = {};
    const float* Wt = (LAYER == 0) ? &d_wT1[0][0] : (LAYER == 1 ? &d_wT2[0][0] : &d_wT3[0][0]);
    const float* fb = feat + (size_t)b * C * N;
    const float* Xb = (LAYER == 1) ? &d_y1[b][0][0] : &d_y2[b][0][0];

    int bkk = tid >> 4;                  // load row (0..15)
    int bn4 = (tid & 15) * 4;            // load col base

    float4 ra, rb;
    {   // prefetch k0 = 0
        ra = *(const float4*)&Wt[bkk * M + m0 + bn4];
        int row = bkk;
        if (LAYER == 0) {
            if (row < 3) rb = *(const float4*)&d_gxyz[b][row][n0 + bn4];
            else {
                const float* fr = fb + (size_t)(row - 3) * N;
                rb.x = __ldg(fr + s_inds[bn4 + 0]);
                rb.y = __ldg(fr + s_inds[bn4 + 1]);
                rb.z = __ldg(fr + s_inds[bn4 + 2]);
                rb.w = __ldg(fr + s_inds[bn4 + 3]);
            }
        } else {
            rb = *(const float4*)&Xb[(size_t)row * NS + n0 + bn4];
        }
    }

    for (int k0 = 0; k0 < K; k0 += KT) {
        *(float4*)&As[bkk][bn4] = ra;
        if (LAYER > 0) {
            float a = s_scale[k0 + bkk], h = s_shift[k0 + bkk];
            rb.x = fmaxf(fmaf(a, rb.x, h), 0.f);
            rb.y = fmaxf(fmaf(a, rb.y, h), 0.f);
            rb.z = fmaxf(fmaf(a, rb.z, h), 0.f);
            rb.w = fmaxf(fmaf(a, rb.w, h), 0.f);
        }
        *(float4*)&Bs[bkk][bn4] = rb;
        __syncthreads();

        if (k0 + KT < K) {
            int kn = k0 + KT;
            ra = *(const float4*)&Wt[(kn + bkk) * M + m0 + bn4];
            int row = kn + bkk;
            if (LAYER == 0) {
                if (row < 3) rb = *(const float4*)&d_gxyz[b][row][n0 + bn4];
                else if (row < K1) {
                    const float* fr = fb + (size_t)(row - 3) * N;
                    rb.x = __ldg(fr + s_inds[bn4 + 0]);
                    rb.y = __ldg(fr + s_inds[bn4 + 1]);
                    rb.z = __ldg(fr + s_inds[bn4 + 2]);
                    rb.w = __ldg(fr + s_inds[bn4 + 3]);
                } else {
                    rb = make_float4(0.f, 0.f, 0.f, 0.f);
                }
            } else {
                rb = *(const float4*)&Xb[(size_t)row * NS + n0 + bn4];
            }
        }

        #pragma unroll
        for (int kk = 0; kk < KT; kk++) {
            float4 a0 = *(float4*)&As[kk][tm];
            float4 bb = *(float4*)&Bs[kk][tn];
            float av[4] = {a0.x, a0.y, a0.z, a0.w};
            float bv[4] = {bb.x, bb.y, bb.z, bb.w};
            #pragma unroll
            for (int i = 0; i < 4; i++)
                #pragma unroll
                for (int j = 0; j < 4; j++)
                    acc[i][j] = fmaf(av[i], bv[j], acc[i][j]);
        }
        __syncthreads();
    }

    // epilogue
    float* Yb = (LAYER == 0) ? &d_y1[b][0][0] : &d_y2[b][0][0];
    float rmax[4], rmin[4];
    #pragma unroll
    for (int i = 0; i < 4; i++) {
        float bi = bias[m0 + tm + i];
        float s = 0.f, s2 = 0.f, mx = -3.0e38f, mnv = 3.0e38f;
        #pragma unroll
        for (int j = 0; j < 4; j++) {
            float v = acc[i][j] + bi;
            acc[i][j] = v;
            s += v; s2 += v * v;
            mx = fmaxf(mx, v); mnv = fminf(mnv, v);
        }
        if (LAYER < 2)
            *(float4*)&Yb[(size_t)(m0 + tm + i) * NS + n0 + tn] =
                make_float4(acc[i][0], acc[i][1], acc[i][2], acc[i][3]);
        red [g][tm + i] = s;
        red2[g][tm + i] = s2;
        rmax[i] = mx; rmin[i] = mnv;
    }
    __syncthreads();
    if (tid < MH) {
        float s = 0.f, s2 = 0.f;
        #pragma unroll
        for (int gg = 0; gg < 16; gg++) { s += red[gg][tid]; s2 += red2[gg][tid]; }
        atomicAdd(&d_sum [LAYER][m0 + tid], s);
        atomicAdd(&d_sum2[LAYER][m0 + tid], s2);
    }
    if (LAYER == 2) {
        __syncthreads();
        #pragma unroll
        for (int i = 0; i < 4; i++) { red[g][tm + i] = rmax[i]; red2[g][tm + i] = rmin[i]; }
        __syncthreads();
        if (tid < MH) {
            float mx = -3.0e38f, mnv = 3.0e38f;
            #pragma unroll
            for (int gg = 0; gg < 16; gg++) { mx = fmaxf(mx, red[gg][tid]); mnv = fminf(mnv, red2[gg][tid]); }
            atomicMax(&d_maxenc[b][m0 + tid], enc(mx));
            atomicMin(&d_minenc[b][m0 + tid], enc(mnv));
        }
    }
}

// ---- THE kernel: everything in one launch ---------------------------------
__global__ void __launch_bounds__(256, 2)
fused_kernel(const float* __restrict__ xyz,
             const float* __restrict__ feat,
             const float* __restrict__ w1,  const float* __restrict__ b1,
             const float* __restrict__ g1,  const float* __restrict__ be1,
             const float* __restrict__ w2,  const float* __restrict__ b2,
             const float* __restrict__ g2,  const float* __restrict__ be2,
             const float* __restrict__ w3,  const float* __restrict__ b3,
             const float* __restrict__ g3,  const float* __restrict__ be3,
             const float* __restrict__ hw1, const float* __restrict__ hb1,
             const float* __restrict__ hg1, const float* __restrict__ hbe1,
             const float* __restrict__ hw2, const float* __restrict__ hb2,
             const float* __restrict__ hg2, const float* __restrict__ hbe2,
             const float* __restrict__ hw3, const float* __restrict__ hb3,
             float* __restrict__ out)
{
    __shared__ float As[KT][MH];
    __shared__ float Bs[KT][NT];
    __shared__ float red [16][MH + 1];
    __shared__ float red2[16][MH + 1];
    __shared__ float s_scale[M], s_shift[M];
    __shared__ int   s_inds[NT];
    __shared__ unsigned s_sense;
    __shared__ int   s_wsum[8];

    int blk = blockIdx.x;
    int tid = threadIdx.x;               // 256

    if (tid == 0) s_sense = atomicAdd(&g_sense, 0u);

    // ---------------- phase 0: setup -----------------------------------
    if (blk < B) {
        // ballquery for batch b = blk (256 threads, 256 pts each)
        int b = blk;
        const float* x = xyz + (size_t)b * N * 3;
        float cx = x[0], cy = x[1], cz = x[2];
        int lane = tid & 31, warp = tid >> 5;

        unsigned long long mask[4] = {0ull, 0ull, 0ull, 0ull};
        int cnt = 0;
        const float* base = x + (size_t)tid * PPT * 3;
        #pragma unroll
        for (int jj = 0; jj < 4; jj++) {
            #pragma unroll 8
            for (int i = 0; i < 64; i++) {
                int p = jj * 64 + i;
                float dx = base[p*3+0] - cx;
                float dy = base[p*3+1] - cy;
                float dz = base[p*3+2] - cz;
                if (dx*dx + dy*dy + dz*dz < 1.0f) { mask[jj] |= (1ull << i); cnt++; }
            }
        }
        // 256-thread scan
        int incl = cnt;
        #pragma unroll
        for (int o = 1; o < 32; o <<= 1) {
            int t2 = __shfl_up_sync(0xffffffffu, incl, o);
            if (lane >= o) incl += t2;
        }
        if (lane == 31) s_wsum[warp] = incl;
        __syncthreads();
        if (tid < 8) {
            int v = s_wsum[tid];
            #pragma unroll
            for (int o = 1; o < 8; o <<= 1) {
                int t2 = __shfl_up_sync(0xffu, v, o);
                if (tid >= o) v += t2;
            }
            s_wsum[tid] = v;
        }
        __syncthreads();
        int excl = incl - cnt + (warp ? s_wsum[warp - 1] : 0);
        int total = s_wsum[7];

        if (excl < NS) {
            int pos = excl;
            #pragma unroll
            for (int jj = 0; jj < 4 && pos < NS; jj++) {
                unsigned long long m = mask[jj];
                while (m && pos < NS) {
                    int i = __ffsll((long long)m) - 1;
                    d_inds[b][pos++] = tid * PPT + jj * 64 + i;
                    m &= (m - 1);
                }
            }
        }
        for (int p = min(total, NS) + tid; p < NS; p += 256) d_inds[b][p] = 0;
        __syncthreads();
        for (int n = tid; n < NS; n += 256) {
            int id = d_inds[b][n];
            d_gxyz[b][0][n] = x[id*3+0] - cx;
            d_gxyz[b][1][n] = x[id*3+1] - cy;
            d_gxyz[b][2][n] = x[id*3+2] - cz;
        }
    } else if (blk < B + 16) {
        // prep: transpose weights, zero accumulators (16 blocks x 256 thr)
        int gtid = (blk - B) * 256 + tid;
        int nthr = 16 * 256;
        for (int i = gtid; i < 3 * M; i += nthr) { (&d_sum[0][0])[i] = 0.f; (&d_sum2[0][0])[i] = 0.f; }
        for (int i = gtid; i < B * M; i += nthr) { (&d_maxenc[0][0])[i] = 0u; (&d_minenc[0][0])[i] = 0xFFFFFFFFu; }
        for (int i = gtid; i < KP * M; i += nthr) {
            int k = i / M, m = i % M;
            d_wT1[k][m] = (k < K1) ? w1[m * K1 + k] : 0.f;
        }
        for (int i = gtid; i < M * M; i += nthr) {
            int k = i / M, m = i % M;
            d_wT2[k][m] = w2[m * M + k];
            d_wT3[k][m] = w3[m * M + k];
        }
    }
    gbar(&s_sense);

    // ---------------- phases 1-3: the three conv layers -----------------
    gemm_phase<KP, 0>(feat, b1, nullptr, nullptr, As, Bs, red, red2, s_scale, s_shift, s_inds);
    gbar(&s_sense);
    gemm_phase<M, 1>(feat, b2, g1, be1, As, Bs, red, red2, s_scale, s_shift, s_inds);
    gbar(&s_sense);
    gemm_phase<M, 2>(feat, b3, g2, be2, As, Bs, red, red2, s_scale, s_shift, s_inds);
    gbar(&s_sense);

    // ---------------- phase 4: head (block 0 only) -----------------------
    if (blk == 0) {
        float* sf = &red [0][0];      // reuse smem: 1024 floats
        float* z  = &red2[0][0];      // 1024 floats
        float* sa = s_scale, *sb_ = s_shift;

        if (tid < M) {
            float inv = 1.0f / (float)(B * NS);
            float mn  = d_sum [2][tid] * inv;
            float var = d_sum2[2][tid] * inv - mn * mn;
            float a = g3[tid] * rsqrtf(var + EPS);
            sa[tid] = a;
            sb_[tid] = be3[tid] - mn * a;
        }
        __syncthreads();
        for (int it = tid; it < B * M; it += 256) {     // maxpool via extrema
            int o = it & 127;
            float a = sa[o], d = sb_[o];
            float mx = dec((&d_maxenc[0][0])[it]);
            float mnv = dec((&d_minenc[0][0])[it]);
            float v = (a >= 0.f) ? fmaf(a, mx, d) : fmaf(a, mnv, d);
            sf[it] = fmaxf(v, 0.f);
        }
        __syncthreads();

        // layer 1
        for (int it = tid; it < B * M; it += 256) {
            int b = it >> 7, o = it & 127;
            float acc = hb1[o];
            #pragma unroll 8
            for (int k = 0; k < M; k++) acc = fmaf(sf[b * M + k], hw1[o * M + k], acc);
            z[it] = acc;
        }
        __syncthreads();
        if (tid < M) {
            float s = 0.f, s2 = 0.f;
            for (int bb = 0; bb < B; bb++) { float v = z[bb * M + tid]; s += v; s2 += v * v; }
            float mn = s * 0.125f, var = s2 * 0.125f - mn * mn;
            float a = hg1[tid] * rsqrtf(var + EPS);
            sa[tid] = a; sb_[tid] = hbe1[tid] - mn * a;
        }
        __syncthreads();
        for (int it = tid; it < B * M; it += 256) {
            int o = it & 127;
            sf[it] = fmaxf(fmaf(sa[o], z[it], sb_[o]), 0.f);
        }
        __syncthreads();

        // layer 2
        for (int it = tid; it < B * M; it += 256) {
            int b = it >> 7, o = it & 127;
            float acc = hb2[o];
            #pragma unroll 8
            for (int k = 0; k < M; k++) acc = fmaf(sf[b * M + k], hw2[o * M + k], acc);
            z[it] = acc;
        }
        __syncthreads();
        if (tid < M) {
            float s = 0.f, s2 = 0.f;
            for (int bb = 0; bb < B; bb++) { float v = z[bb * M + tid]; s += v; s2 += v * v; }
            float mn = s * 0.125f, var = s2 * 0.125f - mn * mn;
            float a = hg2[tid] * rsqrtf(var + EPS);
            sa[tid] = a; sb_[tid] = hbe2[tid] - mn * a;
        }
        __syncthreads();
        for (int it = tid; it < B * M; it += 256) {
            int o = it & 127;
            sf[it] = fmaxf(fmaf(sa[o], z[it], sb_[o]), 0.f);
        }
        __syncthreads();

        // layer 3: 8 x 12 outputs
        if (tid < B * 12) {
            int bb = tid / 12, oo = tid % 12;
            float acc = hb3[oo];
            #pragma unroll 8
            for (int k = 0; k < M; k++) acc = fmaf(sf[bb * M + k], hw3[oo * M + k], acc);
            if (oo < 3)      out[bb * 3 + oo]            = xyz[(size_t)bb * N * 3 + oo] + acc;
            else if (oo < 6) out[24 + bb * 3 + (oo - 3)] = acc;
            else             out[48 + bb * 6 + (oo - 6)] = acc;
        }
    }
}

// ---------------- launch ---------------------------------------------------
extern "C" void kernel_launch(void* const* d_in, const int* in_sizes, int n_in,
                              void* d_out, int out_size) {
    const float* xyz  = (const float*)d_in[0];
    const float* feat = (const float*)d_in[1];
    fused_kernel<<<NB, 256>>>(
        xyz, feat,
        (const float*)d_in[2],  (const float*)d_in[3],  (const float*)d_in[4],  (const float*)d_in[5],
        (const float*)d_in[6],  (const float*)d_in[7],  (const float*)d_in[8],  (const float*)d_in[9],
        (const float*)d_in[10], (const float*)d_in[11], (const float*)d_in[12], (const float*)d_in[13],
        (const float*)d_in[14], (const float*)d_in[15], (const float*)d_in[16], (const float*)d_in[17],
        (const float*)d_in[18], (const float*)d_in[19], (const float*)d_in[20], (const float*)d_in[21],
        (const float*)d_in[22], (const float*)d_in[23],
        (float*)d_out);
}

// round 8
// speedup vs baseline: 1.9464x; 1.9464x over previous
#include <cuda_runtime.h>
#include <cuda_bf16.h>
#include <cstdint>

#define B 8
#define N 65536
#define C 256
#define NS 1024
#define K1 259              // real K of layer 1 (3 xyz + 256 feat)
#define KP 272              // padded K (multiple of 16)
#define M 128
#define MH 64               // M per block
#define NT 64
#define KT 16
#define EPS 1e-5f
#define CH 2048             // ballquery chunk (points)

// ---------------- scratch (device globals; no allocs) ---------------------
__device__ __align__(256) int      d_inds[B][NS];
__device__ __align__(256) float    d_g [B][KP][NS];   // rows 0-2 xyz, 3-258 feat, 259+ zero
__device__ __align__(256) float    d_y1[B][M][NS];
__device__ __align__(256) float    d_y2[B][M][NS];
__device__ __align__(256) float    d_wT1[KP][M];
__device__ __align__(256) float    d_wT2[M][M];
__device__ __align__(256) float    d_wT3[M][M];
__device__ __align__(256) float    d_hT1[M][M];
__device__ __align__(256) float    d_hT2[M][M];
__device__ __align__(256) float    d_sum [3][M];
__device__ __align__(256) float    d_sum2[3][M];
__device__ __align__(256) unsigned d_maxenc[B][M];
__device__ __align__(256) unsigned d_minenc[B][M];

__device__ __forceinline__ unsigned enc(float f) {
    unsigned u = __float_as_uint(f);
    return (u & 0x80000000u) ? ~u : (u | 0x80000000u);
}
__device__ __forceinline__ float dec(unsigned u) {
    return __uint_as_float((u & 0x80000000u) ? (u ^ 0x80000000u) : ~u);
}

// ---------- 0) setup: blocks 0-7 ballquery (coalesced chunks), 8-23 prep ---
__global__ void __launch_bounds__(256)
setup_kernel(const float* __restrict__ xyz,
             const float* __restrict__ w1,
             const float* __restrict__ w2,
             const float* __restrict__ w3,
             const float* __restrict__ hw1,
             const float* __restrict__ hw2) {
    int blk = blockIdx.x;
    int tid = threadIdx.x;

    if (blk >= B) {
        // ---- prep: transposes + zeroing (16 blocks x 256 thr) ----
        int gtid = (blk - B) * 256 + tid;
        int nthr = 16 * 256;
        for (int i = gtid; i < 3 * M; i += nthr) { (&d_sum[0][0])[i] = 0.f; (&d_sum2[0][0])[i] = 0.f; }
        for (int i = gtid; i < B * M; i += nthr) { (&d_maxenc[0][0])[i] = 0u; (&d_minenc[0][0])[i] = 0xFFFFFFFFu; }
        // zero padding rows of d_g (k = 259..271)
        for (int i = gtid; i < B * (KP - K1) * NS; i += nthr) {
            int b = i / ((KP - K1) * NS);
            int r = i % ((KP - K1) * NS);
            d_g[b][K1 + r / NS][r % NS] = 0.f;
        }
        for (int i = gtid; i < KP * M; i += nthr) {
            int k = i / M, m = i % M;
            d_wT1[k][m] = (k < K1) ? w1[m * K1 + k] : 0.f;
        }
        for (int i = gtid; i < M * M; i += nthr) {
            int k = i / M, m = i % M;
            d_wT2[k][m] = w2[m * M + k];
            d_wT3[k][m] = w3[m * M + k];
            d_hT1[k][m] = hw1[m * M + k];
            d_hT2[k][m] = hw2[m * M + k];
        }
        return;
    }

    // ---- ballquery for batch b = blk: chunked, smem-staged, early exit ----
    int b = blk;
    const float* x = xyz + (size_t)b * N * 3;
    float cx = x[0], cy = x[1], cz = x[2];
    int lane = tid & 31, warp = tid >> 5;

    __shared__ float4 s_stage[CH * 3 / 4];   // 24KB
    __shared__ int s_wsum[8];
    __shared__ int s_base;
    if (tid == 0) s_base = 0;
    __syncthreads();

    const float* sp = (const float*)s_stage;
    for (int c0 = 0; c0 < N; c0 += CH) {
        // coalesced stage: 1536 float4 / 256 thr = 6 each
        const float4* src = (const float4*)(x + (size_t)c0 * 3);
        #pragma unroll
        for (int j = 0; j < 6; j++)
            s_stage[tid + 256 * j] = src[tid + 256 * j];
        int base = s_base;                    // safe: published before last sync
        __syncthreads();

        // validity of 8 contiguous points per thread
        unsigned msk = 0; int cnt = 0;
        #pragma unroll
        for (int j = 0; j < 8; j++) {
            int p = tid * 8 + j;
            float dx = sp[p*3+0] - cx;
            float dy = sp[p*3+1] - cy;
            float dz = sp[p*3+2] - cz;
            if (dx*dx + dy*dy + dz*dz < 1.0f) { msk |= (1u << j); cnt++; }
        }
        // block scan
        int incl = cnt;
        #pragma unroll
        for (int o = 1; o < 32; o <<= 1) {
            int t2 = __shfl_up_sync(0xffffffffu, incl, o);
            if (lane >= o) incl += t2;
        }
        if (lane == 31) s_wsum[warp] = incl;
        __syncthreads();
        if (tid < 8) {
            int v = s_wsum[tid];
            #pragma unroll
            for (int o = 1; o < 8; o <<= 1) {
                int t2 = __shfl_up_sync(0xffu, v, o);
                if (tid >= o) v += t2;
            }
            s_wsum[tid] = v;
        }
        __syncthreads();
        int excl = incl - cnt + (warp ? s_wsum[warp - 1] : 0);
        int total = s_wsum[7];

        // emit (ascending order by construction)
        int pos = base + excl;
        unsigned m = msk;
        while (m && pos < NS) {
            int j = __ffs(m) - 1;
            d_inds[b][pos++] = c0 + tid * 8 + j;
            m &= (m - 1);
        }
        __syncthreads();
        if (tid == 0) s_base = base + total;
        if (base + total >= NS) { __syncthreads(); break; }
        __syncthreads();
    }

    __syncthreads();
    int count = min(s_base, NS);
    for (int p = count + tid; p < NS; p += 256) d_inds[b][p] = 0;  // idx 0 always valid
    __syncthreads();

    // xyz rows of g
    for (int n = tid; n < NS; n += 256) {
        int id = d_inds[b][n];
        d_g[b][0][n] = x[id*3+0] - cx;
        d_g[b][1][n] = x[id*3+1] - cy;
        d_g[b][2][n] = x[id*3+2] - cz;
    }
}

// ---------------- 1) feature gather (high-MLP, once per element) ----------
__global__ void __launch_bounds__(256)
gather_kernel(const float* __restrict__ feat) {
    int c = blockIdx.x;                 // 0..255
    int b = blockIdx.y;
    int tid = threadIdx.x;              // 256
    const float* fp = feat + ((size_t)b * C + c) * N;
    int n = tid * 4;
    int4 idx = *(const int4*)&d_inds[b][n];
    float4 v;
    v.x = __ldg(fp + idx.x);
    v.y = __ldg(fp + idx.y);
    v.z = __ldg(fp + idx.z);
    v.w = __ldg(fp + idx.w);
    *(float4*)&d_g[b][3 + c][n] = v;
}

// ---------------- 2) fused GEMM + BN-prev + stats(+extrema) ---------------
template<int K, int LAYER>
__global__ void __launch_bounds__(256)
gemm_kernel(const float* __restrict__ bias,
            const float* __restrict__ gamma_prev,
            const float* __restrict__ beta_prev) {
    __shared__ float As[KT][MH];
    __shared__ float Bs[KT][NT];
    __shared__ float red [16][MH + 1];
    __shared__ float red2[16][MH + 1];
    __shared__ float s_scale[M], s_shift[M];

    int n0 = blockIdx.x * NT;
    int m0 = blockIdx.y * MH;
    int b  = blockIdx.z;
    int tid = threadIdx.x;               // 256
    int tm = (tid & 15) * 4;
    int tn = (tid >> 4) * 4;
    int g  = tid >> 4;

    if (LAYER > 0) {
        if (tid < M) {
            float inv = 1.0f / (float)(B * NS);
            float mn  = d_sum [LAYER-1][tid] * inv;
            float var = d_sum2[LAYER-1][tid] * inv - mn * mn;
            float a = gamma_prev[tid] * rsqrtf(var + EPS);
            s_scale[tid] = a;
            s_shift[tid] = beta_prev[tid] - mn * a;
        }
        __syncthreads();
    }

    float acc[4][4] = {};
    const float* Wt = (LAYER == 0) ? &d_wT1[0][0] : (LAYER == 1 ? &d_wT2[0][0] : &d_wT3[0][0]);
    const float* Xb = (LAYER == 0) ? &d_g[b][0][0] : (LAYER == 1 ? &d_y1[b][0][0] : &d_y2[b][0][0]);

    int bkk = tid >> 4;                  // load row (0..15)
    int bn4 = (tid & 15) * 4;            // load col base

    float4 ra, rb;
    ra = *(const float4*)&Wt[bkk * M + m0 + bn4];
    rb = *(const float4*)&Xb[(size_t)bkk * NS + n0 + bn4];

    for (int k0 = 0; k0 < K; k0 += KT) {
        *(float4*)&As[bkk][bn4] = ra;
        if (LAYER > 0) {
            float a = s_scale[k0 + bkk], h = s_shift[k0 + bkk];
            rb.x = fmaxf(fmaf(a, rb.x, h), 0.f);
            rb.y = fmaxf(fmaf(a, rb.y, h), 0.f);
            rb.z = fmaxf(fmaf(a, rb.z, h), 0.f);
            rb.w = fmaxf(fmaf(a, rb.w, h), 0.f);
        }
        *(float4*)&Bs[bkk][bn4] = rb;
        __syncthreads();

        if (k0 + KT < K) {
            int kn = k0 + KT;
            ra = *(const float4*)&Wt[(kn + bkk) * M + m0 + bn4];
            rb = *(const float4*)&Xb[(size_t)(kn + bkk) * NS + n0 + bn4];
        }

        #pragma unroll
        for (int kk = 0; kk < KT; kk++) {
            float4 a0 = *(float4*)&As[kk][tm];
            float4 bb = *(float4*)&Bs[kk][tn];
            float av[4] = {a0.x, a0.y, a0.z, a0.w};
            float bv[4] = {bb.x, bb.y, bb.z, bb.w};
            #pragma unroll
            for (int i = 0; i < 4; i++)
                #pragma unroll
                for (int j = 0; j < 4; j++)
                    acc[i][j] = fmaf(av[i], bv[j], acc[i][j]);
        }
        __syncthreads();
    }

    // epilogue
    float* Yb = (LAYER == 0) ? &d_y1[b][0][0] : &d_y2[b][0][0];
    float rmax[4], rmin[4];
    #pragma unroll
    for (int i = 0; i < 4; i++) {
        float bi = bias[m0 + tm + i];
        float s = 0.f, s2 = 0.f, mx = -3.0e38f, mnv = 3.0e38f;
        #pragma unroll
        for (int j = 0; j < 4; j++) {
            float v = acc[i][j] + bi;
            acc[i][j] = v;
            s += v; s2 += v * v;
            mx = fmaxf(mx, v); mnv = fminf(mnv, v);
        }
        if (LAYER < 2)
            *(float4*)&Yb[(size_t)(m0 + tm + i) * NS + n0 + tn] =
                make_float4(acc[i][0], acc[i][1], acc[i][2], acc[i][3]);
        red [g][tm + i] = s;
        red2[g][tm + i] = s2;
        rmax[i] = mx; rmin[i] = mnv;
    }
    __syncthreads();
    if (tid < MH) {
        float s = 0.f, s2 = 0.f;
        #pragma unroll
        for (int gg = 0; gg < 16; gg++) { s += red[gg][tid]; s2 += red2[gg][tid]; }
        atomicAdd(&d_sum [LAYER][m0 + tid], s);
        atomicAdd(&d_sum2[LAYER][m0 + tid], s2);
    }
    if (LAYER == 2) {
        __syncthreads();
        #pragma unroll
        for (int i = 0; i < 4; i++) { red[g][tm + i] = rmax[i]; red2[g][tm + i] = rmin[i]; }
        __syncthreads();
        if (tid < MH) {
            float mx = -3.0e38f, mnv = 3.0e38f;
            #pragma unroll
            for (int gg = 0; gg < 16; gg++) { mx = fmaxf(mx, red[gg][tid]); mnv = fminf(mnv, red2[gg][tid]); }
            atomicMax(&d_maxenc[b][m0 + tid], enc(mx));
            atomicMin(&d_minenc[b][m0 + tid], enc(mnv));
        }
    }
}

// ---------------- 3) FC head (1024 thr; transposed weights) ----------------
__global__ void __launch_bounds__(1024)
head_kernel(const float* __restrict__ xyz,
            const float* __restrict__ g3,  const float* __restrict__ be3,
            const float* __restrict__ hb1,
            const float* __restrict__ hg1, const float* __restrict__ hbe1,
            const float* __restrict__ hb2,
            const float* __restrict__ hg2, const float* __restrict__ hbe2,
            const float* __restrict__ hw3, const float* __restrict__ hb3,
            float* __restrict__ out) {
    __shared__ float sf[B][M];
    __shared__ float z [B][M];
    __shared__ float sa[M], sb_[M];
    int tid = threadIdx.x;          // 1024
    int b = tid >> 7, o = tid & 127;

    if (tid < M) {                  // finalize BN3 affine
        float inv = 1.0f / (float)(B * NS);
        float mn  = d_sum [2][tid] * inv;
        float var = d_sum2[2][tid] * inv - mn * mn;
        float a = g3[tid] * rsqrtf(var + EPS);
        sa[tid] = a;
        sb_[tid] = be3[tid] - mn * a;
    }
    __syncthreads();
    {   // maxpool via extrema (exact for either sign of gamma)
        float a = sa[o], d = sb_[o];
        float mx = dec(d_maxenc[b][o]);
        float mnv = dec(d_minenc[b][o]);
        float v = (a >= 0.f) ? fmaf(a, mx, d) : fmaf(a, mnv, d);
        sf[b][o] = fmaxf(v, 0.f);
    }
    __syncthreads();

    // layer 1 (coalesced transposed weight reads)
    {
        float acc = hb1[o];
        #pragma unroll 8
        for (int k = 0; k < M; k++) acc = fmaf(sf[b][k], d_hT1[k][o], acc);
        z[b][o] = acc;
    }
    __syncthreads();
    if (tid < M) {
        float s = 0.f, s2 = 0.f;
        for (int bb = 0; bb < B; bb++) { float v = z[bb][tid]; s += v; s2 += v * v; }
        float mn = s * 0.125f, var = s2 * 0.125f - mn * mn;
        float a = hg1[tid] * rsqrtf(var + EPS);
        sa[tid] = a; sb_[tid] = hbe1[tid] - mn * a;
    }
    __syncthreads();
    sf[b][o] = fmaxf(fmaf(sa[o], z[b][o], sb_[o]), 0.f);
    __syncthreads();

    // layer 2
    {
        float acc = hb2[o];
        #pragma unroll 8
        for (int k = 0; k < M; k++) acc = fmaf(sf[b][k], d_hT2[k][o], acc);
        z[b][o] = acc;
    }
    __syncthreads();
    if (tid < M) {
        float s = 0.f, s2 = 0.f;
        for (int bb = 0; bb < B; bb++) { float v = z[bb][tid]; s += v; s2 += v * v; }
        float mn = s * 0.125f, var = s2 * 0.125f - mn * mn;
        float a = hg2[tid] * rsqrtf(var + EPS);
        sa[tid] = a; sb_[tid] = hbe2[tid] - mn * a;
    }
    __syncthreads();
    sf[b][o] = fmaxf(fmaf(sa[o], z[b][o], sb_[o]), 0.f);
    __syncthreads();

    // layer 3: 8 x 12 outputs
    if (tid < B * 12) {
        int bb = tid / 12, oo = tid % 12;
        float acc = hb3[oo];
        #pragma unroll 8
        for (int k = 0; k < M; k++) acc = fmaf(sf[bb][k], hw3[oo * M + k], acc);
        if (oo < 3)      out[bb * 3 + oo]            = xyz[(size_t)bb * N * 3 + oo] + acc;
        else if (oo < 6) out[24 + bb * 3 + (oo - 3)] = acc;
        else             out[48 + bb * 6 + (oo - 6)] = acc;
    }
}

// ---------------- launch ---------------------------------------------------
extern "C" void kernel_launch(void* const* d_in, const int* in_sizes, int n_in,
                              void* d_out, int out_size) {
    const float* xyz  = (const float*)d_in[0];
    const float* feat = (const float*)d_in[1];
    const float* w1   = (const float*)d_in[2];
    const float* b1   = (const float*)d_in[3];
    const float* g1   = (const float*)d_in[4];
    const float* be1  = (const float*)d_in[5];
    const float* w2   = (const float*)d_in[6];
    const float* b2   = (const float*)d_in[7];
    const float* g2   = (const float*)d_in[8];
    const float* be2  = (const float*)d_in[9];
    const float* w3   = (const float*)d_in[10];
    const float* b3   = (const float*)d_in[11];
    const float* g3   = (const float*)d_in[12];
    const float* be3  = (const float*)d_in[13];
    const float* hw1  = (const float*)d_in[14];
    const float* hb1  = (const float*)d_in[15];
    const float* hg1  = (const float*)d_in[16];
    const float* hbe1 = (const float*)d_in[17];
    const float* hw2  = (const float*)d_in[18];
    const float* hb2  = (const float*)d_in[19];
    const float* hg2  = (const float*)d_in[20];
    const float* hbe2 = (const float*)d_in[21];
    const float* hw3  = (const float*)d_in[22];
    const float* hb3  = (const float*)d_in[23];
    float* out = (float*)d_out;

    setup_kernel<<<B + 16, 256>>>(xyz, w1, w2, w3, hw1, hw2);
    gather_kernel<<<dim3(C, B), 256>>>(feat);

    dim3 gemm_grid(NS / NT, M / MH, B);      // (16, 2, 8) = 256 blocks
    gemm_kernel<KP, 0><<<gemm_grid, 256>>>(b1, nullptr, nullptr);
    gemm_kernel<M,  1><<<gemm_grid, 256>>>(b2, g1, be1);
    gemm_kernel<M,  2><<<gemm_grid, 256>>>(b3, g2, be2);

    head_kernel<<<1, 1024>>>(xyz, g3, be3,
                             hb1, hg1, hbe1,
                             hb2, hg2, hbe2, hw3, hb3, out);
}

// round 12
// speedup vs baseline: 2.0221x; 1.0389x over previous
#include <cuda_runtime.h>
#include <cuda_bf16.h>
#include <cstdint>

#define B 8
#define N 65536
#define C 256
#define NS 1024
#define K1 259              // real K of layer 1 (3 xyz + 256 feat)
#define KP 272              // padded K (multiple of 16)
#define M 128
#define MH 64               // M per block
#define NT 64
#define KT 16
#define EPS 1e-5f
#define CH 2048             // ballquery chunk (points)

// ---------------- scratch (device globals; no allocs) ---------------------
__device__ __align__(256) int      d_inds[B][NS];
__device__ __align__(256) float    d_g [B][KP][NS];   // rows 0-2 xyz, 3-258 feat, 259+ zero
__device__ __align__(256) float    d_y1[B][M][NS];
__device__ __align__(256) float    d_y2[B][M][NS];
__device__ __align__(256) float    d_wT1[KP][M];
__device__ __align__(256) float    d_wT2[M][M];
__device__ __align__(256) float    d_wT3[M][M];
__device__ __align__(256) float    d_hT1[M][M];
__device__ __align__(256) float    d_hT2[M][M];
__device__ __align__(256) float    d_sum [3][M];
__device__ __align__(256) float    d_sum2[3][M];
__device__ __align__(256) unsigned d_maxenc[B][M];
__device__ __align__(256) unsigned d_minenc[B][M];

__device__ __forceinline__ unsigned enc(float f) {
    unsigned u = __float_as_uint(f);
    return (u & 0x80000000u) ? ~u : (u | 0x80000000u);
}
__device__ __forceinline__ float dec(unsigned u) {
    return __uint_as_float((u & 0x80000000u) ? (u ^ 0x80000000u) : ~u);
}

// ---- packed fp32x2 helpers (sm_103a; bit-exact dual FMA) ------------------
__device__ __forceinline__ unsigned long long pk2(float lo, float hi) {
    unsigned long long o;
    asm("mov.b64 %0, {%1, %2};" : "=l"(o) : "f"(lo), "f"(hi));
    return o;
}
#define FFMA2(d, a, b) \
    asm("fma.rn.f32x2 %0, %1, %2, %3;" : "=l"(d) : "l"(a), "l"(b), "l"(d))
__device__ __forceinline__ void unpk2(unsigned long long v, float& lo, float& hi) {
    asm("mov.b64 {%0, %1}, %2;" : "=f"(lo), "=f"(hi) : "l"(v));
}

// ---------- 0) setup: blocks 0-7 ballquery (coalesced chunks), 8-23 prep ---
__global__ void __launch_bounds__(256)
setup_kernel(const float* __restrict__ xyz,
             const float* __restrict__ w1,
             const float* __restrict__ w2,
             const float* __restrict__ w3,
             const float* __restrict__ hw1,
             const float* __restrict__ hw2) {
    int blk = blockIdx.x;
    int tid = threadIdx.x;

    if (blk >= B) {
        // ---- prep: coalesced-READ transposes + zeroing (16 blocks) ----
        int gtid = (blk - B) * 256 + tid;
        int nthr = 16 * 256;
        for (int i = gtid; i < 3 * M; i += nthr) { (&d_sum[0][0])[i] = 0.f; (&d_sum2[0][0])[i] = 0.f; }
        for (int i = gtid; i < B * M; i += nthr) { (&d_maxenc[0][0])[i] = 0u; (&d_minenc[0][0])[i] = 0xFFFFFFFFu; }
        // zero padding rows of d_g (k = 259..271)
        for (int i = gtid; i < B * (KP - K1) * NS; i += nthr) {
            int b = i / ((KP - K1) * NS);
            int r = i % ((KP - K1) * NS);
            d_g[b][K1 + r / NS][r % NS] = 0.f;
        }
        // w1 transpose: consecutive threads take consecutive k -> coalesced reads
        for (int i = gtid; i < M * KP; i += nthr) {
            int m = i / KP, k = i % KP;
            d_wT1[k][m] = (k < K1) ? w1[m * K1 + k] : 0.f;
        }
        for (int i = gtid; i < M * M; i += nthr) {
            int m = i >> 7, k = i & 127;          // coalesced source reads
            d_wT2[k][m] = w2[m * M + k];
            d_wT3[k][m] = w3[m * M + k];
            d_hT1[k][m] = hw1[m * M + k];
            d_hT2[k][m] = hw2[m * M + k];
        }
        return;
    }

    // ---- ballquery for batch b = blk: chunked, smem-staged, early exit ----
    int b = blk;
    const float* x = xyz + (size_t)b * N * 3;
    float cx = x[0], cy = x[1], cz = x[2];
    int lane = tid & 31, warp = tid >> 5;

    __shared__ float4 s_stage[CH * 3 / 4];   // 24KB
    __shared__ int s_wsum[8];
    __shared__ int s_base;
    if (tid == 0) s_base = 0;
    __syncthreads();

    const float* sp = (const float*)s_stage;
    for (int c0 = 0; c0 < N; c0 += CH) {
        const float4* src = (const float4*)(x + (size_t)c0 * 3);
        #pragma unroll
        for (int j = 0; j < 6; j++)
            s_stage[tid + 256 * j] = src[tid + 256 * j];
        int base = s_base;
        __syncthreads();

        unsigned msk = 0; int cnt = 0;
        #pragma unroll
        for (int j = 0; j < 8; j++) {
            int p = tid * 8 + j;
            float dx = sp[p*3+0] - cx;
            float dy = sp[p*3+1] - cy;
            float dz = sp[p*3+2] - cz;
            if (dx*dx + dy*dy + dz*dz < 1.0f) { msk |= (1u << j); cnt++; }
        }
        int incl = cnt;
        #pragma unroll
        for (int o = 1; o < 32; o <<= 1) {
            int t2 = __shfl_up_sync(0xffffffffu, incl, o);
            if (lane >= o) incl += t2;
        }
        if (lane == 31) s_wsum[warp] = incl;
        __syncthreads();
        if (tid < 8) {
            int v = s_wsum[tid];
            #pragma unroll
            for (int o = 1; o < 8; o <<= 1) {
                int t2 = __shfl_up_sync(0xffu, v, o);
                if (tid >= o) v += t2;
            }
            s_wsum[tid] = v;
        }
        __syncthreads();
        int excl = incl - cnt + (warp ? s_wsum[warp - 1] : 0);
        int total = s_wsum[7];

        int pos = base + excl;
        unsigned m = msk;
        while (m && pos < NS) {
            int j = __ffs(m) - 1;
            d_inds[b][pos++] = c0 + tid * 8 + j;
            m &= (m - 1);
        }
        __syncthreads();
        if (tid == 0) s_base = base + total;
        if (base + total >= NS) { __syncthreads(); break; }
        __syncthreads();
    }

    __syncthreads();
    int count = min(s_base, NS);
    for (int p = count + tid; p < NS; p += 256) d_inds[b][p] = 0;
    __syncthreads();

    for (int n = tid; n < NS; n += 256) {
        int id = d_inds[b][n];
        d_g[b][0][n] = x[id*3+0] - cx;
        d_g[b][1][n] = x[id*3+1] - cy;
        d_g[b][2][n] = x[id*3+2] - cz;
    }
}

// ---------------- 1) feature gather (MLP=8 per thread) --------------------
__global__ void __launch_bounds__(128)
gather_kernel(const float* __restrict__ feat) {
    int c = blockIdx.x;                 // 0..255
    int b = blockIdx.y;
    int tid = threadIdx.x;              // 128
    const float* fp = feat + ((size_t)b * C + c) * N;
    int n = tid * 8;
    int4 i0 = *(const int4*)&d_inds[b][n];
    int4 i1 = *(const int4*)&d_inds[b][n + 4];
    float4 v0, v1;
    v0.x = __ldg(fp + i0.x); v0.y = __ldg(fp + i0.y);
    v0.z = __ldg(fp + i0.z); v0.w = __ldg(fp + i0.w);
    v1.x = __ldg(fp + i1.x); v1.y = __ldg(fp + i1.y);
    v1.z = __ldg(fp + i1.z); v1.w = __ldg(fp + i1.w);
    *(float4*)&d_g[b][3 + c][n]     = v0;
    *(float4*)&d_g[b][3 + c][n + 4] = v1;
}

// ---------------- 2) fused GEMM (fp32x2) + BN-prev + stats(+extrema) ------
template<int K, int LAYER>
__global__ void __launch_bounds__(256)
gemm_kernel(const float* __restrict__ bias,
            const float* __restrict__ gamma_prev,
            const float* __restrict__ beta_prev) {
    __shared__ float As[KT][MH];
    __shared__ float Bs[KT][NT];
    __shared__ float red [16][MH + 1];
    __shared__ float red2[16][MH + 1];
    __shared__ float s_scale[M], s_shift[M];

    int n0 = blockIdx.x * NT;
    int m0 = blockIdx.y * MH;
    int b  = blockIdx.z;
    int tid = threadIdx.x;               // 256
    int tm = (tid & 15) * 4;
    int tn = (tid >> 4) * 4;
    int g  = tid >> 4;

    if (LAYER > 0) {
        if (tid < M) {
            float inv = 1.0f / (float)(B * NS);
            float mn  = d_sum [LAYER-1][tid] * inv;
            float var = d_sum2[LAYER-1][tid] * inv - mn * mn;
            float a = gamma_prev[tid] * rsqrtf(var + EPS);
            s_scale[tid] = a;
            s_shift[tid] = beta_prev[tid] - mn * a;
        }
        __syncthreads();
    }

    unsigned long long acc2[4][2] = {};
    const float* Wt = (LAYER == 0) ? &d_wT1[0][0] : (LAYER == 1 ? &d_wT2[0][0] : &d_wT3[0][0]);
    const float* Xb = (LAYER == 0) ? &d_g[b][0][0] : (LAYER == 1 ? &d_y1[b][0][0] : &d_y2[b][0][0]);

    int bkk = tid >> 4;                  // load row (0..15)
    int bn4 = (tid & 15) * 4;            // load col base

    float4 ra, rb;
    ra = *(const float4*)&Wt[bkk * M + m0 + bn4];
    rb = *(const float4*)&Xb[(size_t)bkk * NS + n0 + bn4];

    for (int k0 = 0; k0 < K; k0 += KT) {
        *(float4*)&As[bkk][bn4] = ra;
        if (LAYER > 0) {
            float a = s_scale[k0 + bkk], h = s_shift[k0 + bkk];
            rb.x = fmaxf(fmaf(a, rb.x, h), 0.f);
            rb.y = fmaxf(fmaf(a, rb.y, h), 0.f);
            rb.z = fmaxf(fmaf(a, rb.z, h), 0.f);
            rb.w = fmaxf(fmaf(a, rb.w, h), 0.f);
        }
        *(float4*)&Bs[bkk][bn4] = rb;
        __syncthreads();

        if (k0 + KT < K) {
            int kn = k0 + KT;
            ra = *(const float4*)&Wt[(kn + bkk) * M + m0 + bn4];
            rb = *(const float4*)&Xb[(size_t)(kn + bkk) * NS + n0 + bn4];
        }

        #pragma unroll
        for (int kk = 0; kk < KT; kk++) {
            float4 a0 = *(float4*)&As[kk][tm];
            float4 bb = *(float4*)&Bs[kk][tn];
            unsigned long long b01 = pk2(bb.x, bb.y);
            unsigned long long b23 = pk2(bb.z, bb.w);
            unsigned long long aa;
            aa = pk2(a0.x, a0.x); FFMA2(acc2[0][0], aa, b01); FFMA2(acc2[0][1], aa, b23);
            aa = pk2(a0.y, a0.y); FFMA2(acc2[1][0], aa, b01); FFMA2(acc2[1][1], aa, b23);
            aa = pk2(a0.z, a0.z); FFMA2(acc2[2][0], aa, b01); FFMA2(acc2[2][1], aa, b23);
            aa = pk2(a0.w, a0.w); FFMA2(acc2[3][0], aa, b01); FFMA2(acc2[3][1], aa, b23);
        }
        __syncthreads();
    }

    // unpack accumulators
    float acc[4][4];
    #pragma unroll
    for (int i = 0; i < 4; i++) {
        unpk2(acc2[i][0], acc[i][0], acc[i][1]);
        unpk2(acc2[i][1], acc[i][2], acc[i][3]);
    }

    // epilogue
    float* Yb = (LAYER == 0) ? &d_y1[b][0][0] : &d_y2[b][0][0];
    float rmax[4], rmin[4];
    #pragma unroll
    for (int i = 0; i < 4; i++) {
        float bi = bias[m0 + tm + i];
        float s = 0.f, s2 = 0.f, mx = -3.0e38f, mnv = 3.0e38f;
        #pragma unroll
        for (int j = 0; j < 4; j++) {
            float v = acc[i][j] + bi;
            acc[i][j] = v;
            s += v; s2 += v * v;
            mx = fmaxf(mx, v); mnv = fminf(mnv, v);
        }
        if (LAYER < 2)
            *(float4*)&Yb[(size_t)(m0 + tm + i) * NS + n0 + tn] =
                make_float4(acc[i][0], acc[i][1], acc[i][2], acc[i][3]);
        red [g][tm + i] = s;
        red2[g][tm + i] = s2;
        rmax[i] = mx; rmin[i] = mnv;
    }
    __syncthreads();
    if (tid < MH) {
        float s = 0.f, s2 = 0.f;
        #pragma unroll
        for (int gg = 0; gg < 16; gg++) { s += red[gg][tid]; s2 += red2[gg][tid]; }
        atomicAdd(&d_sum [LAYER][m0 + tid], s);
        atomicAdd(&d_sum2[LAYER][m0 + tid], s2);
    }
    if (LAYER == 2) {
        __syncthreads();
        #pragma unroll
        for (int i = 0; i < 4; i++) { red[g][tm + i] = rmax[i]; red2[g][tm + i] = rmin[i]; }
        __syncthreads();
        if (tid < MH) {
            float mx = -3.0e38f, mnv = 3.0e38f;
            #pragma unroll
            for (int gg = 0; gg < 16; gg++) { mx = fmaxf(mx, red[gg][tid]); mnv = fminf(mnv, red2[gg][tid]); }
            atomicMax(&d_maxenc[b][m0 + tid], enc(mx));
            atomicMin(&d_minenc[b][m0 + tid], enc(mnv));
        }
    }
}

// ---------------- 3) FC head (1024 thr; transposed weights) ----------------
__global__ void __launch_bounds__(1024)
head_kernel(const float* __restrict__ xyz,
            const float* __restrict__ g3,  const float* __restrict__ be3,
            const float* __restrict__ hb1,
            const float* __restrict__ hg1, const float* __restrict__ hbe1,
            const float* __restrict__ hb2,
            const float* __restrict__ hg2, const float* __restrict__ hbe2,
            const float* __restrict__ hw3, const float* __restrict__ hb3,
            float* __restrict__ out) {
    __shared__ float sf[B][M];
    __shared__ float z [B][M];
    __shared__ float sa[M], sb_[M];
    int tid = threadIdx.x;          // 1024
    int b = tid >> 7, o = tid & 127;

    if (tid < M) {
        float inv = 1.0f / (float)(B * NS);
        float mn  = d_sum [2][tid] * inv;
        float var = d_sum2[2][tid] * inv - mn * mn;
        float a = g3[tid] * rsqrtf(var + EPS);
        sa[tid] = a;
        sb_[tid] = be3[tid] - mn * a;
    }
    __syncthreads();
    {
        float a = sa[o], d = sb_[o];
        float mx = dec(d_maxenc[b][o]);
        float mnv = dec(d_minenc[b][o]);
        float v = (a >= 0.f) ? fmaf(a, mx, d) : fmaf(a, mnv, d);
        sf[b][o] = fmaxf(v, 0.f);
    }
    __syncthreads();

    // layer 1
    {
        float acc = hb1[o];
        #pragma unroll 16
        for (int k = 0; k < M; k++) acc = fmaf(sf[b][k], d_hT1[k][o], acc);
        z[b][o] = acc;
    }
    __syncthreads();
    if (tid < M) {
        float s = 0.f, s2 = 0.f;
        for (int bb = 0; bb < B; bb++) { float v = z[bb][tid]; s += v; s2 += v * v; }
        float mn = s * 0.125f, var = s2 * 0.125f - mn * mn;
        float a = hg1[tid] * rsqrtf(var + EPS);
        sa[tid] = a; sb_[tid] = hbe1[tid] - mn * a;
    }
    __syncthreads();
    sf[b][o] = fmaxf(fmaf(sa[o], z[b][o], sb_[o]), 0.f);
    __syncthreads();

    // layer 2
    {
        float acc = hb2[o];
        #pragma unroll 16
        for (int k = 0; k < M; k++) acc = fmaf(sf[b][k], d_hT2[k][o], acc);
        z[b][o] = acc;
    }
    __syncthreads();
    if (tid < M) {
        float s = 0.f, s2 = 0.f;
        for (int bb = 0; bb < B; bb++) { float v = z[bb][tid]; s += v; s2 += v * v; }
        float mn = s * 0.125f, var = s2 * 0.125f - mn * mn;
        float a = hg2[tid] * rsqrtf(var + EPS);
        sa[tid] = a; sb_[tid] = hbe2[tid] - mn * a;
    }
    __syncthreads();
    sf[b][o] = fmaxf(fmaf(sa[o], z[b][o], sb_[o]), 0.f);
    __syncthreads();

    // layer 3: 8 x 12 outputs
    if (tid < B * 12) {
        int bb = tid / 12, oo = tid % 12;
        float acc = hb3[oo];
        #pragma unroll 16
        for (int k = 0; k < M; k++) acc = fmaf(sf[bb][k], hw3[oo * M + k], acc);
        if (oo < 3)      out[bb * 3 + oo]            = xyz[(size_t)bb * N * 3 + oo] + acc;
        else if (oo < 6) out[24 + bb * 3 + (oo - 3)] = acc;
        else             out[48 + bb * 6 + (oo - 6)] = acc;
    }
}

// ---------------- launch ---------------------------------------------------
extern "C" void kernel_launch(void* const* d_in, const int* in_sizes, int n_in,
                              void* d_out, int out_size) {
    const float* xyz  = (const float*)d_in[0];
    const float* feat = (const float*)d_in[1];
    const float* w1   = (const float*)d_in[2];
    const float* b1   = (const float*)d_in[3];
    const float* g1   = (const float*)d_in[4];
    const float* be1  = (const float*)d_in[5];
    const float* w2   = (const float*)d_in[6];
    const float* b2   = (const float*)d_in[7];
    const float* g2   = (const float*)d_in[8];
    const float* be2  = (const float*)d_in[9];
    const float* w3   = (const float*)d_in[10];
    const float* b3   = (const float*)d_in[11];
    const float* g3   = (const float*)d_in[12];
    const float* be3  = (const float*)d_in[13];
    const float* hw1  = (const float*)d_in[14];
    const float* hb1  = (const float*)d_in[15];
    const float* hg1  = (const float*)d_in[16];
    const float* hbe1 = (const float*)d_in[17];
    const float* hw2  = (const float*)d_in[18];
    const float* hb2  = (const float*)d_in[19];
    const float* hg2  = (const float*)d_in[20];
    const float* hbe2 = (const float*)d_in[21];
    const float* hw3  = (const float*)d_in[22];
    const float* hb3  = (const float*)d_in[23];
    float* out = (float*)d_out;

    setup_kernel<<<B + 16, 256>>>(xyz, w1, w2, w3, hw1, hw2);
    gather_kernel<<<dim3(C, B), 128>>>(feat);

    dim3 gemm_grid(NS / NT, M / MH, B);      // (16, 2, 8) = 256 blocks
    gemm_kernel<KP, 0><<<gemm_grid, 256>>>(b1, nullptr, nullptr);
    gemm_kernel<M,  1><<<gemm_grid, 256>>>(b2, g1, be1);
    gemm_kernel<M,  2><<<gemm_grid, 256>>>(b3, g2, be2);

    head_kernel<<<1, 1024>>>(xyz, g3, be3,
                             hb1, hg1, hbe1,
                             hb2, hg2, hbe2, hw3, hb3, out);
}